// round 8
// baseline (speedup 1.0000x reference)
#include <cuda_runtime.h>
#include <cuda_bf16.h>
#include <cstdio>

// ============================================================================
// DiseaseGraphEncoder: input proj -> 2x RGCN(basis) -> readout (mean+max MLP)
//                      + node projection.
//
// Strategy:
//   msg_e = sum_b coeffs[et_e,b] * (h[src_e] @ bases[b])
// Hoist basis matmuls to node level: Y = h @ concat(bases) (N x 256), then the
// per-edge work is a 4-coeff combine of Y[src] + atomic scatter-add into agg.
// agg is pre-seeded with the self term (h @ Wself + bself) by the same GEMM.
// ReLU is applied lazily on reads.
// ============================================================================

#define NNODES 100000
#define NEDGES 1000000
#define HID 64

// -------------------- device scratch (no allocation allowed) ----------------
__device__ float g_h0  [(size_t)NNODES * 64];
__device__ float g_Y   [(size_t)NNODES * 256];
__device__ float g_aggA[(size_t)NNODES * 64];
__device__ float g_aggB[(size_t)NNODES * 64];
__device__ float g_psum[256 * 64];
__device__ float g_pmax[256 * 64];

// -------------------- input projection: (N,15) @ (15,64) + b ----------------
__global__ void inproj_kernel(const float* __restrict__ nf,
                              const float* __restrict__ W,
                              const float* __restrict__ b)
{
    __shared__ float Ws[15 * 64];
    __shared__ float bs[64];
    __shared__ float nfs[4 * 15];
    int tid = threadIdx.x;
    for (int i = tid; i < 15 * 64; i += 256) Ws[i] = W[i];
    if (tid < 64) bs[tid] = b[tid];
    int n0 = blockIdx.x * 4;
    if (tid < 60) {
        int node = n0 + tid / 15;
        nfs[tid] = (node < NNODES) ? nf[(size_t)node * 15 + (tid % 15)] : 0.f;
    }
    __syncthreads();
    int l = tid >> 6, j = tid & 63;
    int node = n0 + l;
    if (node < NNODES) {
        float s = bs[j];
#pragma unroll
        for (int k = 0; k < 15; k++) s += nfs[l * 15 + k] * Ws[k * 64 + j];
        g_h0[(size_t)node * 64 + j] = s;
    }
}

// -------------------- layer GEMM: Y = h @ [bases|*], agg = h@Wself + bself --
// grid = (ceil(N/64), 5); col tiles 0..3 -> Y (256 cols), tile 4 -> self (64).
__global__ void layer_gemm_kernel(const float* __restrict__ h,
                                  const float* __restrict__ bases,   // (4,64,64)
                                  const float* __restrict__ Wself,   // (64,64)
                                  const float* __restrict__ bself,   // (64)
                                  float* __restrict__ Y,
                                  float* __restrict__ agg,
                                  int relu_in)
{
    __shared__ float As[64 * 65];   // [k][m], padded
    __shared__ float Bs[64 * 64];   // [k][c]
    int m0  = blockIdx.x * 64;
    int ct  = blockIdx.y;           // 0..4
    int tid = threadIdx.x;

    // load A tile (coalesced on k), store transposed [k][m]
    {
        int k = tid & 63;
        int mb = tid >> 6;
        for (int mm = mb; mm < 64; mm += 4) {
            int node = m0 + mm;
            float v = 0.f;
            if (node < NNODES) {
                v = h[(size_t)node * 64 + k];
                if (relu_in) v = fmaxf(v, 0.f);
            }
            As[k * 65 + mm] = v;
        }
    }
    // load B tile [k][c]
    {
        int c  = tid & 63;
        int kb = tid >> 6;
        int gc = ct * 64 + c;
        for (int k = kb; k < 64; k += 4) {
            float v;
            if (gc < 256) {
                int bidx = gc >> 6, j = gc & 63;
                v = bases[bidx * 4096 + k * 64 + j];
            } else {
                v = Wself[k * 64 + (gc - 256)];
            }
            Bs[k * 64 + c] = v;
        }
    }
    __syncthreads();

    int tm0 = (tid >> 4) * 4;
    int tn0 = (tid & 15) * 4;
    float acc[4][4] = {};
#pragma unroll 8
    for (int k = 0; k < 64; k++) {
        float a0 = As[k * 65 + tm0 + 0];
        float a1 = As[k * 65 + tm0 + 1];
        float a2 = As[k * 65 + tm0 + 2];
        float a3 = As[k * 65 + tm0 + 3];
        float4 b4 = *reinterpret_cast<const float4*>(&Bs[k * 64 + tn0]);
        acc[0][0] += a0 * b4.x; acc[0][1] += a0 * b4.y; acc[0][2] += a0 * b4.z; acc[0][3] += a0 * b4.w;
        acc[1][0] += a1 * b4.x; acc[1][1] += a1 * b4.y; acc[1][2] += a1 * b4.z; acc[1][3] += a1 * b4.w;
        acc[2][0] += a2 * b4.x; acc[2][1] += a2 * b4.y; acc[2][2] += a2 * b4.z; acc[2][3] += a2 * b4.w;
        acc[3][0] += a3 * b4.x; acc[3][1] += a3 * b4.y; acc[3][2] += a3 * b4.z; acc[3][3] += a3 * b4.w;
    }

    int gc0 = ct * 64 + tn0;
#pragma unroll
    for (int i = 0; i < 4; i++) {
        int node = m0 + tm0 + i;
        if (node >= NNODES) continue;
        if (ct < 4) {
            float4 o = make_float4(acc[i][0], acc[i][1], acc[i][2], acc[i][3]);
            *reinterpret_cast<float4*>(&Y[(size_t)node * 256 + gc0]) = o;
        } else {
            int j = gc0 - 256;
            float4 o = make_float4(acc[i][0] + bself[j + 0],
                                   acc[i][1] + bself[j + 1],
                                   acc[i][2] + bself[j + 2],
                                   acc[i][3] + bself[j + 3]);
            *reinterpret_cast<float4*>(&agg[(size_t)node * 64 + j]) = o;
        }
    }
}

// -------------------- edge scatter: warp per edge ---------------------------
__global__ void edge_kernel(const float* __restrict__ Y,
                            const int* __restrict__ src,
                            const int* __restrict__ tgt,
                            const int* __restrict__ et,
                            const float* __restrict__ coeffs,  // (13,4)
                            float* __restrict__ agg)
{
    __shared__ float csm[52];
    if (threadIdx.x < 52) csm[threadIdx.x] = coeffs[threadIdx.x];
    __syncthreads();
    int e    = (blockIdx.x * blockDim.x + threadIdx.x) >> 5;
    int lane = threadIdx.x & 31;
    if (e >= NEDGES) return;
    int s = src[e], t = tgt[e], r = et[e];
    float c0 = csm[r * 4 + 0], c1 = csm[r * 4 + 1];
    float c2 = csm[r * 4 + 2], c3 = csm[r * 4 + 3];
    const float* y = Y + (size_t)s * 256;
    float m1 = c0 * y[lane]      + c1 * y[lane + 64]
             + c2 * y[lane + 128] + c3 * y[lane + 192];
    float m2 = c0 * y[lane + 32] + c1 * y[lane + 96]
             + c2 * y[lane + 160] + c3 * y[lane + 224];
    float* a = agg + (size_t)t * 64;
    atomicAdd(a + lane,      m1);
    atomicAdd(a + lane + 32, m2);
}

// -------------------- plain GEMM (node_emb): C = relu(h) @ W + bias ---------
// grid = (ceil(N/64), ncols/64)
__global__ void gemm_out_kernel(const float* __restrict__ h,
                                const float* __restrict__ W,     // (64, ncols)
                                const float* __restrict__ bias,  // (ncols)
                                float* __restrict__ C, int ncols)
{
    __shared__ float As[64 * 65];
    __shared__ float Bs[64 * 64];
    int m0  = blockIdx.x * 64;
    int ct  = blockIdx.y;
    int tid = threadIdx.x;
    {
        int k = tid & 63;
        int mb = tid >> 6;
        for (int mm = mb; mm < 64; mm += 4) {
            int node = m0 + mm;
            float v = 0.f;
            if (node < NNODES) v = fmaxf(h[(size_t)node * 64 + k], 0.f);
            As[k * 65 + mm] = v;
        }
    }
    {
        int c  = tid & 63;
        int kb = tid >> 6;
        int gc = ct * 64 + c;
        for (int k = kb; k < 64; k += 4)
            Bs[k * 64 + c] = W[k * ncols + gc];
    }
    __syncthreads();

    int tm0 = (tid >> 4) * 4;
    int tn0 = (tid & 15) * 4;
    float acc[4][4] = {};
#pragma unroll 8
    for (int k = 0; k < 64; k++) {
        float a0 = As[k * 65 + tm0 + 0];
        float a1 = As[k * 65 + tm0 + 1];
        float a2 = As[k * 65 + tm0 + 2];
        float a3 = As[k * 65 + tm0 + 3];
        float4 b4 = *reinterpret_cast<const float4*>(&Bs[k * 64 + tn0]);
        acc[0][0] += a0 * b4.x; acc[0][1] += a0 * b4.y; acc[0][2] += a0 * b4.z; acc[0][3] += a0 * b4.w;
        acc[1][0] += a1 * b4.x; acc[1][1] += a1 * b4.y; acc[1][2] += a1 * b4.z; acc[1][3] += a1 * b4.w;
        acc[2][0] += a2 * b4.x; acc[2][1] += a2 * b4.y; acc[2][2] += a2 * b4.z; acc[2][3] += a2 * b4.w;
        acc[3][0] += a3 * b4.x; acc[3][1] += a3 * b4.y; acc[3][2] += a3 * b4.z; acc[3][3] += a3 * b4.w;
    }
    int gc0 = ct * 64 + tn0;
    float bx = bias[gc0 + 0], by = bias[gc0 + 1], bz = bias[gc0 + 2], bw = bias[gc0 + 3];
#pragma unroll
    for (int i = 0; i < 4; i++) {
        int node = m0 + tm0 + i;
        if (node >= NNODES) continue;
        float4 o = make_float4(acc[i][0] + bx, acc[i][1] + by,
                               acc[i][2] + bz, acc[i][3] + bw);
        *reinterpret_cast<float4*>(&C[(size_t)node * ncols + gc0]) = o;
    }
}

// -------------------- pooling: per-block partial sum/max of relu(h) ---------
__global__ void pool_partial_kernel(const float* __restrict__ h)
{
    __shared__ float ss[256], sm[256];
    int tid = threadIdx.x;
    int col = tid & 63, r = tid >> 6;
    float s = 0.f, mx = 0.f;
    for (int node = blockIdx.x * 4 + r; node < NNODES; node += gridDim.x * 4) {
        float v = fmaxf(h[(size_t)node * 64 + col], 0.f);
        s += v; mx = fmaxf(mx, v);
    }
    ss[tid] = s; sm[tid] = mx;
    __syncthreads();
    if (tid < 128) { ss[tid] += ss[tid + 128]; sm[tid] = fmaxf(sm[tid], sm[tid + 128]); }
    __syncthreads();
    if (tid < 64) {
        g_psum[blockIdx.x * 64 + col] = ss[tid] + ss[tid + 64];
        g_pmax[blockIdx.x * 64 + col] = fmaxf(sm[tid], sm[tid + 64]);
    }
}

// -------------------- final reduce + readout MLP (1 block, 128 thr) ---------
__global__ void pool_final_kernel(const float* __restrict__ Wr1,
                                  const float* __restrict__ br1,
                                  const float* __restrict__ Wr2,
                                  const float* __restrict__ br2,
                                  float* __restrict__ out)
{
    __shared__ float g[128], t[64];
    int tid = threadIdx.x;
    if (tid < 64) {
        float s = 0.f, mx = 0.f;
        for (int b = 0; b < 256; b++) {
            s += g_psum[b * 64 + tid];
            mx = fmaxf(mx, g_pmax[b * 64 + tid]);
        }
        g[tid]      = s / (float)NNODES;
        g[64 + tid] = mx;
    }
    __syncthreads();
    if (tid < 64) {
        float acc = br1[tid];
#pragma unroll 8
        for (int k = 0; k < 128; k++) acc += g[k] * Wr1[k * 64 + tid];
        t[tid] = fmaxf(acc, 0.f);
    }
    __syncthreads();
    {
        float acc = br2[tid];
#pragma unroll 8
        for (int i = 0; i < 64; i++) acc += t[i] * Wr2[i * 128 + tid];
        out[tid] = acc;
    }
}

// ============================================================================
extern "C" void kernel_launch(void* const* d_in, const int* in_sizes, int n_in,
                              void* d_out, int out_size)
{
    const float* nf     = (const float*)d_in[0];
    const int*   eidx   = (const int*)  d_in[1];
    const int*   etype  = (const int*)  d_in[2];
    const float* W_in   = (const float*)d_in[3];
    const float* b_in   = (const float*)d_in[4];
    const float* Wself0 = (const float*)d_in[5];
    const float* bself0 = (const float*)d_in[6];
    const float* bases0 = (const float*)d_in[7];
    const float* coef0  = (const float*)d_in[8];
    const float* Wself1 = (const float*)d_in[9];
    const float* bself1 = (const float*)d_in[10];
    const float* bases1 = (const float*)d_in[11];
    const float* coef1  = (const float*)d_in[12];
    const float* Wr1    = (const float*)d_in[13];
    const float* br1    = (const float*)d_in[14];
    const float* Wr2    = (const float*)d_in[15];
    const float* br2    = (const float*)d_in[16];
    const float* Wnp    = (const float*)d_in[17];
    const float* bnp    = (const float*)d_in[18];
    float* out = (float*)d_out;

    const int* src = eidx;
    const int* tgt = eidx + NEDGES;

    float *p_h0, *p_Y, *p_aggA, *p_aggB;
    cudaGetSymbolAddress((void**)&p_h0,   g_h0);
    cudaGetSymbolAddress((void**)&p_Y,    g_Y);
    cudaGetSymbolAddress((void**)&p_aggA, g_aggA);
    cudaGetSymbolAddress((void**)&p_aggB, g_aggB);

    int mtiles = (NNODES + 63) / 64;

    // 1. input projection
    inproj_kernel<<<(NNODES + 3) / 4, 256>>>(nf, W_in, b_in);

    // 2. layer 0: Y + self seed, then edge scatter
    layer_gemm_kernel<<<dim3(mtiles, 5), 256>>>(p_h0, bases0, Wself0, bself0,
                                                p_Y, p_aggA, /*relu=*/0);
    edge_kernel<<<(NEDGES * 32 + 255) / 256, 256>>>(p_Y, src, tgt, etype, coef0, p_aggA);

    // 3. layer 1 (reads relu(aggA))
    layer_gemm_kernel<<<dim3(mtiles, 5), 256>>>(p_aggA, bases1, Wself1, bself1,
                                                p_Y, p_aggB, /*relu=*/1);
    edge_kernel<<<(NEDGES * 32 + 255) / 256, 256>>>(p_Y, src, tgt, etype, coef1, p_aggB);

    // 4. node embeddings: relu(aggB) @ Wnp + bnp -> out[128:]
    gemm_out_kernel<<<dim3(mtiles, 2), 256>>>(p_aggB, Wnp, bnp, out + 128, 128);

    // 5. graph embedding: mean+max pool of relu(aggB) -> MLP -> out[0:128]
    pool_partial_kernel<<<256, 256>>>(p_aggB);
    pool_final_kernel<<<1, 128>>>(Wr1, br1, Wr2, br2, out);
}

// round 11
// speedup vs baseline: 1.2652x; 1.2652x over previous
#include <cuda_runtime.h>
#include <cuda_bf16.h>

// ============================================================================
// DiseaseGraphEncoder: input proj -> 2x RGCN(basis) -> readout + node proj.
//
// R8 restructure: swap basis-transform and aggregation order.
//   agg[t] = sum_b ( sum_{e->t} c[r_e,b] * h[src_e] ) @ B_b  + h[t]@Wself + b
// Phase 1 (gather): CSR by target, warp/node, accumulate U[t] (4x64) in regs.
//   Per-edge read = 256B of h (L2-resident), NO float atomics.
// Phase 2 (GEMM):  A = [U | relu(h)] (N x 320) @ [Bcat ; Wself] (320 x 64).
// CSR built once per call (hist + 2-level scan + scatter), shared by layers.
// ReLU applied lazily on reads.
// ============================================================================

#define NNODES 100000
#define NEDGES 1000000
#define SCAN_B 512
#define NSCANB ((NNODES + SCAN_B - 1) / SCAN_B)   // 196

// -------------------- device scratch (no allocation allowed) ----------------
__device__ float g_h0  [(size_t)NNODES * 64];
__device__ float g_U   [(size_t)NNODES * 320];   // [U0|U1|U2|U3|selfH]
__device__ float g_aggA[(size_t)NNODES * 64];
__device__ float g_aggB[(size_t)NNODES * 64];
__device__ float g_psum[256 * 64];
__device__ float g_pmax[256 * 64];
__device__ int   g_deg   [NNODES];
__device__ int   g_rowptr[NNODES + 1];
__device__ int   g_cursor[NNODES];
__device__ int   g_bsum  [NSCANB];
__device__ int   g_epk   [NEDGES];               // src | (etype << 17)

// ===================== CSR build =====================
__global__ void zero_deg_kernel()
{
    int i = blockIdx.x * blockDim.x + threadIdx.x;
    if (i < NNODES) g_deg[i] = 0;
}

__global__ void hist_kernel(const int* __restrict__ tgt)
{
    int e = blockIdx.x * blockDim.x + threadIdx.x;
    if (e < NEDGES) atomicAdd(&g_deg[tgt[e]], 1);
}

// block-local exclusive scan + block sums
__global__ void scan1_kernel()
{
    __shared__ int s[SCAN_B];
    int i = blockIdx.x * SCAN_B + threadIdx.x;
    int v = (i < NNODES) ? g_deg[i] : 0;
    s[threadIdx.x] = v;
    __syncthreads();
    for (int off = 1; off < SCAN_B; off <<= 1) {
        int t = (threadIdx.x >= off) ? s[threadIdx.x - off] : 0;
        __syncthreads();
        s[threadIdx.x] += t;
        __syncthreads();
    }
    if (i < NNODES) g_rowptr[i] = s[threadIdx.x] - v;   // exclusive
    if (threadIdx.x == SCAN_B - 1) g_bsum[blockIdx.x] = s[threadIdx.x];
}

__global__ void scan2_kernel()   // 1 block, 256 threads (NSCANB=196 <= 256)
{
    __shared__ int s[256];
    int v = (threadIdx.x < NSCANB) ? g_bsum[threadIdx.x] : 0;
    s[threadIdx.x] = v;
    __syncthreads();
    for (int off = 1; off < 256; off <<= 1) {
        int t = (threadIdx.x >= off) ? s[threadIdx.x - off] : 0;
        __syncthreads();
        s[threadIdx.x] += t;
        __syncthreads();
    }
    if (threadIdx.x < NSCANB) g_bsum[threadIdx.x] = s[threadIdx.x] - v;  // exclusive
}

__global__ void scan3_kernel()
{
    int i = blockIdx.x * SCAN_B + threadIdx.x;
    if (i < NNODES) {
        int v = g_rowptr[i] + g_bsum[blockIdx.x];
        g_rowptr[i] = v;
        g_cursor[i] = v;
    }
    if (i == 0) g_rowptr[NNODES] = NEDGES;
}

__global__ void scatter_kernel(const int* __restrict__ src,
                               const int* __restrict__ tgt,
                               const int* __restrict__ et)
{
    int e = blockIdx.x * blockDim.x + threadIdx.x;
    if (e >= NEDGES) return;
    int pos = atomicAdd(&g_cursor[tgt[e]], 1);
    g_epk[pos] = src[e] | (et[e] << 17);
}

// -------------------- input projection: (N,15) @ (15,64) + b ----------------
__global__ void inproj_kernel(const float* __restrict__ nf,
                              const float* __restrict__ W,
                              const float* __restrict__ b)
{
    __shared__ float Ws[15 * 64];
    __shared__ float bs[64];
    __shared__ float nfs[4 * 15];
    int tid = threadIdx.x;
    for (int i = tid; i < 15 * 64; i += 256) Ws[i] = W[i];
    if (tid < 64) bs[tid] = b[tid];
    int n0 = blockIdx.x * 4;
    if (tid < 60) {
        int node = n0 + tid / 15;
        nfs[tid] = (node < NNODES) ? nf[(size_t)node * 15 + (tid % 15)] : 0.f;
    }
    __syncthreads();
    int l = tid >> 6, j = tid & 63;
    int node = n0 + l;
    if (node < NNODES) {
        float s = bs[j];
#pragma unroll
        for (int k = 0; k < 15; k++) s += nfs[l * 15 + k] * Ws[k * 64 + j];
        g_h0[(size_t)node * 64 + j] = s;
    }
}

// ===================== gather: U[t] = sum_e c_b * h[src], warp/node =========
__global__ void gather_kernel(const float* __restrict__ h,
                              const float* __restrict__ coeffs,  // (13,4)
                              float* __restrict__ U,
                              int relu_in)
{
    __shared__ float csm[52];
    if (threadIdx.x < 52) csm[threadIdx.x] = coeffs[threadIdx.x];
    __syncthreads();
    int t    = (blockIdx.x * blockDim.x + threadIdx.x) >> 5;
    int lane = threadIdx.x & 31;
    if (t >= NNODES) return;
    int e   = g_rowptr[t];
    int end = g_rowptr[t + 1];

    float u00 = 0.f, u01 = 0.f, u10 = 0.f, u11 = 0.f;
    float u20 = 0.f, u21 = 0.f, u30 = 0.f, u31 = 0.f;

    if (e < end) {
        int pk = g_epk[e];
        while (true) {
            int s = pk & 0x1FFFF;
            int r = pk >> 17;
            float a = h[(size_t)s * 64 + lane];
            float b = h[(size_t)s * 64 + lane + 32];
            e++;
            bool more = (e < end);
            int pk_n = more ? g_epk[e] : 0;
            if (relu_in) { a = fmaxf(a, 0.f); b = fmaxf(b, 0.f); }
            float c0 = csm[r * 4 + 0], c1 = csm[r * 4 + 1];
            float c2 = csm[r * 4 + 2], c3 = csm[r * 4 + 3];
            u00 += c0 * a; u01 += c0 * b;
            u10 += c1 * a; u11 += c1 * b;
            u20 += c2 * a; u21 += c2 * b;
            u30 += c3 * a; u31 += c3 * b;
            if (!more) break;
            pk = pk_n;
        }
    }

    float* up = U + (size_t)t * 320;
    up[lane +   0] = u00;  up[lane +  32] = u01;
    up[lane +  64] = u10;  up[lane +  96] = u11;
    up[lane + 128] = u20;  up[lane + 160] = u21;
    up[lane + 192] = u30;  up[lane + 224] = u31;
    // self columns: relu?(h[t])
    float a = h[(size_t)t * 64 + lane];
    float b = h[(size_t)t * 64 + lane + 32];
    if (relu_in) { a = fmaxf(a, 0.f); b = fmaxf(b, 0.f); }
    up[lane + 256] = a;
    up[lane + 288] = b;
}

// ===================== layer GEMM: agg = U(Nx320) @ [Bcat;Wself] + bself ====
// grid = ceil(N/64) blocks, 256 threads, 4x4 microtile, K looped in 5 tiles.
__global__ void layer_gemm2_kernel(const float* __restrict__ U,
                                   const float* __restrict__ bases,  // (4,64,64)
                                   const float* __restrict__ Wself,  // (64,64)
                                   const float* __restrict__ bself,
                                   float* __restrict__ agg)
{
    __shared__ float As[64 * 68];   // [k][m], pad 68 keeps float4 alignment
    __shared__ float Bs[64 * 64];   // [k][c]
    int m0  = blockIdx.x * 64;
    int tid = threadIdx.x;
    int tm0 = (tid >> 4) * 4;
    int tn0 = (tid & 15) * 4;
    float acc[4][4] = {};

    for (int kt = 0; kt < 5; kt++) {
        {
            int k  = tid & 63;
            int mb = tid >> 6;
            for (int mm = mb; mm < 64; mm += 4) {
                int node = m0 + mm;
                float v = (node < NNODES) ? U[(size_t)node * 320 + kt * 64 + k] : 0.f;
                As[k * 68 + mm] = v;
            }
        }
        {
            int c  = tid & 63;
            int kb = tid >> 6;
            for (int k = kb; k < 64; k += 4) {
                float v = (kt < 4) ? bases[kt * 4096 + k * 64 + c]
                                   : Wself[k * 64 + c];
                Bs[k * 64 + c] = v;
            }
        }
        __syncthreads();
#pragma unroll 8
        for (int k = 0; k < 64; k++) {
            float4 a4 = *reinterpret_cast<const float4*>(&As[k * 68 + tm0]);
            float4 b4 = *reinterpret_cast<const float4*>(&Bs[k * 64 + tn0]);
            acc[0][0] += a4.x * b4.x; acc[0][1] += a4.x * b4.y; acc[0][2] += a4.x * b4.z; acc[0][3] += a4.x * b4.w;
            acc[1][0] += a4.y * b4.x; acc[1][1] += a4.y * b4.y; acc[1][2] += a4.y * b4.z; acc[1][3] += a4.y * b4.w;
            acc[2][0] += a4.z * b4.x; acc[2][1] += a4.z * b4.y; acc[2][2] += a4.z * b4.z; acc[2][3] += a4.z * b4.w;
            acc[3][0] += a4.w * b4.x; acc[3][1] += a4.w * b4.y; acc[3][2] += a4.w * b4.z; acc[3][3] += a4.w * b4.w;
        }
        __syncthreads();
    }

    float bx = bself[tn0 + 0], by = bself[tn0 + 1];
    float bz = bself[tn0 + 2], bw = bself[tn0 + 3];
#pragma unroll
    for (int i = 0; i < 4; i++) {
        int node = m0 + tm0 + i;
        if (node >= NNODES) continue;
        float4 o = make_float4(acc[i][0] + bx, acc[i][1] + by,
                               acc[i][2] + bz, acc[i][3] + bw);
        *reinterpret_cast<float4*>(&agg[(size_t)node * 64 + tn0]) = o;
    }
}

// -------------------- plain GEMM (node_emb): C = relu(h) @ W + bias ---------
__global__ void gemm_out_kernel(const float* __restrict__ h,
                                const float* __restrict__ W,     // (64, ncols)
                                const float* __restrict__ bias,
                                float* __restrict__ C, int ncols)
{
    __shared__ float As[64 * 68];
    __shared__ float Bs[64 * 64];
    int m0  = blockIdx.x * 64;
    int ct  = blockIdx.y;
    int tid = threadIdx.x;
    {
        int k  = tid & 63;
        int mb = tid >> 6;
        for (int mm = mb; mm < 64; mm += 4) {
            int node = m0 + mm;
            float v = 0.f;
            if (node < NNODES) v = fmaxf(h[(size_t)node * 64 + k], 0.f);
            As[k * 68 + mm] = v;
        }
    }
    {
        int c  = tid & 63;
        int kb = tid >> 6;
        int gc = ct * 64 + c;
        for (int k = kb; k < 64; k += 4)
            Bs[k * 64 + c] = W[k * ncols + gc];
    }
    __syncthreads();

    int tm0 = (tid >> 4) * 4;
    int tn0 = (tid & 15) * 4;
    float acc[4][4] = {};
#pragma unroll 8
    for (int k = 0; k < 64; k++) {
        float4 a4 = *reinterpret_cast<const float4*>(&As[k * 68 + tm0]);
        float4 b4 = *reinterpret_cast<const float4*>(&Bs[k * 64 + tn0]);
        acc[0][0] += a4.x * b4.x; acc[0][1] += a4.x * b4.y; acc[0][2] += a4.x * b4.z; acc[0][3] += a4.x * b4.w;
        acc[1][0] += a4.y * b4.x; acc[1][1] += a4.y * b4.y; acc[1][2] += a4.y * b4.z; acc[1][3] += a4.y * b4.w;
        acc[2][0] += a4.z * b4.x; acc[2][1] += a4.z * b4.y; acc[2][2] += a4.z * b4.z; acc[2][3] += a4.z * b4.w;
        acc[3][0] += a4.w * b4.x; acc[3][1] += a4.w * b4.y; acc[3][2] += a4.w * b4.z; acc[3][3] += a4.w * b4.w;
    }
    int gc0 = ct * 64 + tn0;
    float bx = bias[gc0 + 0], by = bias[gc0 + 1], bz = bias[gc0 + 2], bw = bias[gc0 + 3];
#pragma unroll
    for (int i = 0; i < 4; i++) {
        int node = m0 + tm0 + i;
        if (node >= NNODES) continue;
        float4 o = make_float4(acc[i][0] + bx, acc[i][1] + by,
                               acc[i][2] + bz, acc[i][3] + bw);
        *reinterpret_cast<float4*>(&C[(size_t)node * ncols + gc0]) = o;
    }
}

// -------------------- pooling: per-block partial sum/max of relu(h) ---------
__global__ void pool_partial_kernel(const float* __restrict__ h)
{
    __shared__ float ss[256], sm[256];
    int tid = threadIdx.x;
    int col = tid & 63, r = tid >> 6;
    float s = 0.f, mx = 0.f;
    for (int node = blockIdx.x * 4 + r; node < NNODES; node += gridDim.x * 4) {
        float v = fmaxf(h[(size_t)node * 64 + col], 0.f);
        s += v; mx = fmaxf(mx, v);
    }
    ss[tid] = s; sm[tid] = mx;
    __syncthreads();
    if (tid < 128) { ss[tid] += ss[tid + 128]; sm[tid] = fmaxf(sm[tid], sm[tid + 128]); }
    __syncthreads();
    if (tid < 64) {
        g_psum[blockIdx.x * 64 + col] = ss[tid] + ss[tid + 64];
        g_pmax[blockIdx.x * 64 + col] = fmaxf(sm[tid], sm[tid + 64]);
    }
}

// -------------------- final reduce + readout MLP (1 block, 128 thr) ---------
__global__ void pool_final_kernel(const float* __restrict__ Wr1,
                                  const float* __restrict__ br1,
                                  const float* __restrict__ Wr2,
                                  const float* __restrict__ br2,
                                  float* __restrict__ out)
{
    __shared__ float g[128], t[64];
    int tid = threadIdx.x;
    if (tid < 64) {
        float s = 0.f, mx = 0.f;
        for (int b = 0; b < 256; b++) {
            s += g_psum[b * 64 + tid];
            mx = fmaxf(mx, g_pmax[b * 64 + tid]);
        }
        g[tid]      = s / (float)NNODES;
        g[64 + tid] = mx;
    }
    __syncthreads();
    if (tid < 64) {
        float acc = br1[tid];
#pragma unroll 8
        for (int k = 0; k < 128; k++) acc += g[k] * Wr1[k * 64 + tid];
        t[tid] = fmaxf(acc, 0.f);
    }
    __syncthreads();
    {
        float acc = br2[tid];
#pragma unroll 8
        for (int i = 0; i < 64; i++) acc += t[i] * Wr2[i * 128 + tid];
        out[tid] = acc;
    }
}

// ============================================================================
extern "C" void kernel_launch(void* const* d_in, const int* in_sizes, int n_in,
                              void* d_out, int out_size)
{
    const float* nf     = (const float*)d_in[0];
    const int*   eidx   = (const int*)  d_in[1];
    const int*   etype  = (const int*)  d_in[2];
    const float* W_in   = (const float*)d_in[3];
    const float* b_in   = (const float*)d_in[4];
    const float* Wself0 = (const float*)d_in[5];
    const float* bself0 = (const float*)d_in[6];
    const float* bases0 = (const float*)d_in[7];
    const float* coef0  = (const float*)d_in[8];
    const float* Wself1 = (const float*)d_in[9];
    const float* bself1 = (const float*)d_in[10];
    const float* bases1 = (const float*)d_in[11];
    const float* coef1  = (const float*)d_in[12];
    const float* Wr1    = (const float*)d_in[13];
    const float* br1    = (const float*)d_in[14];
    const float* Wr2    = (const float*)d_in[15];
    const float* br2    = (const float*)d_in[16];
    const float* Wnp    = (const float*)d_in[17];
    const float* bnp    = (const float*)d_in[18];
    float* out = (float*)d_out;

    const int* src = eidx;
    const int* tgt = eidx + NEDGES;

    float *p_h0, *p_U, *p_aggA, *p_aggB;
    cudaGetSymbolAddress((void**)&p_h0,   g_h0);
    cudaGetSymbolAddress((void**)&p_U,    g_U);
    cudaGetSymbolAddress((void**)&p_aggA, g_aggA);
    cudaGetSymbolAddress((void**)&p_aggB, g_aggB);

    int mtiles = (NNODES + 63) / 64;

    // 1. input projection (independent of CSR build, overlaps in graph)
    inproj_kernel<<<(NNODES + 3) / 4, 256>>>(nf, W_in, b_in);

    // 2. CSR build (once, shared by both layers)
    zero_deg_kernel<<<(NNODES + 255) / 256, 256>>>();
    hist_kernel<<<(NEDGES + 255) / 256, 256>>>(tgt);
    scan1_kernel<<<NSCANB, SCAN_B>>>();
    scan2_kernel<<<1, 256>>>();
    scan3_kernel<<<NSCANB, SCAN_B>>>();
    scatter_kernel<<<(NEDGES + 255) / 256, 256>>>(src, tgt, etype);

    // 3. layer 0: gather U from h0, then transform GEMM
    gather_kernel<<<(NNODES * 32 + 255) / 256, 256>>>(p_h0, coef0, p_U, /*relu=*/0);
    layer_gemm2_kernel<<<mtiles, 256>>>(p_U, bases0, Wself0, bself0, p_aggA);

    // 4. layer 1: gather U from relu(aggA), then transform GEMM
    gather_kernel<<<(NNODES * 32 + 255) / 256, 256>>>(p_aggA, coef1, p_U, /*relu=*/1);
    layer_gemm2_kernel<<<mtiles, 256>>>(p_U, bases1, Wself1, bself1, p_aggB);

    // 5. node embeddings: relu(aggB) @ Wnp + bnp -> out[128:]
    gemm_out_kernel<<<dim3(mtiles, 2), 256>>>(p_aggB, Wnp, bnp, out + 128, 128);

    // 6. graph embedding: mean+max pool of relu(aggB) -> MLP -> out[0:128]
    pool_partial_kernel<<<256, 256>>>(p_aggB);
    pool_final_kernel<<<1, 128>>>(Wr1, br1, Wr2, br2, out);
}